// round 6
// baseline (speedup 1.0000x reference)
#include <cuda_runtime.h>
#include <cuda_bf16.h>

// BuzzLoss: B=8192 rows, T=1024 cols.
// R5 structure (256 threads per row, coalesced float4, 8 rows per CTA, one
// barrier per row) with software-pipeline DEPTH 2: rows i+1 and i+2 stay in
// registers while row i runs its scan/barrier, keeping 4 LDG.128 (1 KB) per
// thread outstanding through the latency-exposed phase.

#define FULL_MASK 0xFFFFFFFFu
#define ROWS_PER_CTA 8

__global__ void buzz_zero_kernel(float* out) {
    out[0] = 0.0f;
}

__global__ __launch_bounds__(256)
void buzz_loss_kernel(const float* __restrict__ conf,
                      const float* __restrict__ acc,
                      float* __restrict__ out,
                      float negInvB) {
    const int tid  = threadIdx.x;
    const int lane = tid & 31;
    const int wid  = tid >> 5;
    const size_t row0 = (size_t)blockIdx.x * ROWS_PER_CTA;

    __shared__ float s_wp[2][8];       // per-warp products, double-buffered
    __shared__ float s_accLast[2];
    __shared__ float s_total;

    if (tid == 0) s_total = 0.0f;

    const float4* c4 = reinterpret_cast<const float4*>(conf + row0 * 1024);
    const float4* a4 = reinterpret_cast<const float4*>(acc  + row0 * 1024);

    // pipeline: stage0 = current, stage1 = +1, stage2 = +2
    float4 c0 = c4[tid];
    float4 a0 = a4[tid];
    float4 c1 = c4[256 + tid];
    float4 a1 = a4[256 + tid];

    #pragma unroll
    for (int i = 0; i < ROWS_PER_CTA; i++) {
        const int buf = i & 1;

        // prefetch row i+2 first, before any dependent work / barrier
        float4 c2, a2;
        if (i + 2 < ROWS_PER_CTA) {
            c2 = c4[(i + 2) * 256 + tid];
            a2 = a4[(i + 2) * 256 + tid];
        }

        const float q0 = 1.0f - c0.x;
        const float q1 = 1.0f - c0.y;
        const float q2 = 1.0f - c0.z;

        // warp inclusive product-scan of per-thread 4-element products
        float inc = q0 * q1 * q2 * (1.0f - c0.w);
        #pragma unroll
        for (int d = 1; d < 32; d <<= 1) {
            float v = __shfl_up_sync(FULL_MASK, inc, d);
            if (lane >= d) inc *= v;
        }
        float excl = __shfl_up_sync(FULL_MASK, inc, 1);
        if (lane == 0) excl = 1.0f;

        if (lane == 31) s_wp[buf][wid] = inc;
        if (tid == 255) s_accLast[buf] = a0.w;
        __syncthreads();

        // exclusive product over preceding warps
        float wpref = 1.0f;
        #pragma unroll
        for (int w = 0; w < 7; w++) {
            if (w < wid) wpref *= s_wp[buf][w];
        }
        const float E = wpref * excl;
        const float accLast = s_accLast[buf];

        const float b0 = c0.x * E;
        const float b1 = c0.y * (E * q0);
        const float b2 = c0.z * (E * q0 * q1);
        const float b3 = c0.w * (E * q0 * q1 * q2);

        float s1 = fmaf(b0, a0.x, fmaf(b1, a0.y, fmaf(b2, a0.z, b3 * a0.w)));
        float s2 = (b0 + b1) + (b2 + b3);

        // score = sum s1 - accLast*sum s2 + accLast
        float contrib = fmaf(-accLast, s2, s1);

        #pragma unroll
        for (int d = 16; d >= 1; d >>= 1) {
            contrib += __shfl_down_sync(FULL_MASK, contrib, d);
        }
        if (lane == 0) {
            if (wid == 7) contrib += accLast;
            atomicAdd(&s_total, contrib);
        }

        // rotate pipeline
        c0 = c1; a0 = a1;
        c1 = c2; a1 = a2;
    }

    __syncthreads();
    if (tid == 0) {
        atomicAdd(out, s_total * negInvB);
    }
}

extern "C" void kernel_launch(void* const* d_in, const int* in_sizes, int n_in,
                              void* d_out, int out_size) {
    const float* conf = (const float*)d_in[0];
    const float* acc  = (const float*)d_in[1];
    float* out = (float*)d_out;

    const int total = in_sizes[0];
    const int T = 1024;
    const int B = total / T;

    buzz_zero_kernel<<<1, 1>>>(out);
    buzz_loss_kernel<<<B / ROWS_PER_CTA, 256>>>(conf, acc, out,
                                                -1.0f / (float)B);
}

// round 7
// speedup vs baseline: 1.7881x; 1.7881x over previous
#include <cuda_runtime.h>
#include <cuda_bf16.h>

// BuzzLoss: B=8192 rows, T=1024 cols.
// ONE WARP PER ROW, fully autonomous (no CTA barriers in the hot path).
// Lane l owns elements {j*128 + 4l + e} (j=0..7): every LDG.128 coalesced,
// all 16 loads independent and front-batched -> 8KB in flight per warp.
// The 8 per-segment warp product-scans are independent (ILP across the shfl
// chains); only the 8 cross-segment prefix multiplies are serial.
// Per-CTA smem score accumulation -> 1 global atomic per CTA.

#define FULL_MASK 0xFFFFFFFFu
#define ROWS_PER_CTA 8

__global__ void buzz_zero_kernel(float* out) {
    out[0] = 0.0f;
}

__global__ __launch_bounds__(256)
void buzz_loss_kernel(const float* __restrict__ conf,
                      const float* __restrict__ acc,
                      float* __restrict__ out,
                      float negInvB) {
    const int tid  = threadIdx.x;
    const int lane = tid & 31;
    const int wid  = tid >> 5;
    const size_t row = (size_t)blockIdx.x * ROWS_PER_CTA + wid;

    __shared__ float s_total;
    if (tid == 0) s_total = 0.0f;
    __syncthreads();

    const float4* c4 = reinterpret_cast<const float4*>(conf + row * 1024);
    const float4* a4 = reinterpret_cast<const float4*>(acc  + row * 1024);

    // Front-batched: 16 independent coalesced LDG.128
    float4 c[8], a[8];
    #pragma unroll
    for (int j = 0; j < 8; j++) c[j] = c4[j * 32 + lane];
    #pragma unroll
    for (int j = 0; j < 8; j++) a[j] = a4[j * 32 + lane];

    // Per-segment local 4-element products
    float inc[8];
    #pragma unroll
    for (int j = 0; j < 8; j++) {
        inc[j] = (1.0f - c[j].x) * (1.0f - c[j].y) *
                 (1.0f - c[j].z) * (1.0f - c[j].w);
    }

    // 8 independent warp inclusive product-scans, interleaved for ILP
    #pragma unroll
    for (int d = 1; d < 32; d <<= 1) {
        #pragma unroll
        for (int j = 0; j < 8; j++) {
            float v = __shfl_up_sync(FULL_MASK, inc[j], d);
            if (lane >= d) inc[j] *= v;
        }
    }

    // Cross-segment serial combine (8 multiplies) + accumulation
    float R = 1.0f;         // product of all factors in segments < j
    float s1 = 0.0f, s2 = 0.0f;
    #pragma unroll
    for (int j = 0; j < 8; j++) {
        const float total = __shfl_sync(FULL_MASK, inc[j], 31);
        float E = __shfl_up_sync(FULL_MASK, inc[j], 1);
        if (lane == 0) E = 1.0f;
        E *= R;

        const float q0 = 1.0f - c[j].x;
        const float q1 = 1.0f - c[j].y;
        const float q2 = 1.0f - c[j].z;

        const float b0 = c[j].x * E;
        const float b1 = c[j].y * (E * q0);
        const float b2 = c[j].z * (E * q0 * q1);
        const float b3 = c[j].w * (E * q0 * q1 * q2);

        s1 = fmaf(b0, a[j].x, fmaf(b1, a[j].y,
             fmaf(b2, a[j].z, fmaf(b3, a[j].w, s1))));
        s2 += (b0 + b1) + (b2 + b3);

        R *= total;
    }

    // Warp reduce
    #pragma unroll
    for (int d = 16; d >= 1; d >>= 1) {
        s1 += __shfl_down_sync(FULL_MASK, s1, d);
        s2 += __shfl_down_sync(FULL_MASK, s2, d);
    }
    const float accLast = __shfl_sync(FULL_MASK, a[7].w, 31);

    if (lane == 0) {
        const float score = s1 + (1.0f - s2) * accLast;
        atomicAdd(&s_total, score);
    }

    __syncthreads();
    if (tid == 0) {
        atomicAdd(out, s_total * negInvB);
    }
}

extern "C" void kernel_launch(void* const* d_in, const int* in_sizes, int n_in,
                              void* d_out, int out_size) {
    const float* conf = (const float*)d_in[0];
    const float* acc  = (const float*)d_in[1];
    float* out = (float*)d_out;

    const int total = in_sizes[0];
    const int T = 1024;
    const int B = total / T;

    buzz_zero_kernel<<<1, 1>>>(out);
    buzz_loss_kernel<<<B / ROWS_PER_CTA, 256>>>(conf, acc, out,
                                                -1.0f / (float)B);
}